// round 15
// baseline (speedup 1.0000x reference)
#include <cuda_runtime.h>
#include <cuda_bf16.h>
#include <math.h>
#include <stdint.h>

// ---------------- problem constants ----------------
#define Bq 16
#define Tq 12
#define Nq 1024
#define Dq 128
#define Mq 64
#define TOPKq 16

#define BT (Bq*Tq)                  // 192
#define BTN (BT*Nq)                 // 196608
#define BTND ((size_t)BTN*Dq)       // 25165824
#define NROWS (BT*Mq)               // 12288 topk rows

// ---------------- scratch layout (floats) ----------------
#define OFF_Q    ((size_t)25165824*1)
#define OFF_K    ((size_t)25165824*2)
#define OFF_V    ((size_t)25165824*3)
#define OFF_DICT ((size_t)25165824*4)
#define OFF_VAL  ((size_t)25165824*5)
#define OFF_FF1  ((size_t)25165824*6)
#define OFF_LOG  ((size_t)25165824*7)               // 192*64*1024 = 12582912
#define OFF_CNT  (OFF_LOG + (size_t)12582912)       // 196608
#define OFF_IDX  (OFF_CNT + (size_t)196608)         // 196608 ints
#define OFF_POS  (OFF_IDX + (size_t)196608)         // 131072 floats (pos[n][d])
#define OFF_WBF  (OFF_POS + (size_t)131072)         // 98304 floats = 196608 bf16 (6 weights)
#define OFF_E    (OFF_WBF + (size_t)98304)          // 8192 floats  E[m][k]
#define OFF_C    (OFF_E   + (size_t)8192)           // 64 floats    c[m]
#define TOTAL_SCRATCH (OFF_C + (size_t)64)

__device__ float g_scratch[TOTAL_SCRATCH];

__device__ __forceinline__ uint32_t smem_u32(const void* p) {
    uint32_t a;
    asm("{ .reg .u64 t; cvta.to.shared.u64 t, %1; cvt.u32.u64 %0, t; }" : "=r"(a) : "l"(p));
    return a;
}

enum { EPI_BIAS = 0, EPI_RELU = 1, EPI_LN = 2 };

// ---------------- pos precompute: pos[n][d] = eigvec[d][n] * eigval[d] ----------------
__global__ void pos_kernel(const float* __restrict__ eigvec,
                           const float* __restrict__ eigval,
                           float* __restrict__ posout)
{
    int i = blockIdx.x * 256 + threadIdx.x;   // 0..131071
    int d = i >> 10, n = i & 1023;
    posout[n * Dq + d] = eigvec[(size_t)d * Nq + n] * eigval[d];
}

// ---------------- W bf16 hi/lo split precompute (B = W^T layout [n][k]) ----------------
__global__ void wsplit_kernel(const float* __restrict__ W0, const float* __restrict__ W1,
                              const float* __restrict__ W2, const float* __restrict__ W3,
                              const float* __restrict__ W4, const float* __restrict__ W5,
                              __nv_bfloat16* __restrict__ outb)
{
    int g = blockIdx.x * 256 + threadIdx.x;   // 0..98303
    int w = g >> 14;
    int i = g & 16383;
    int n = i & 127, k = i >> 7;
    const float* W = (w == 0) ? W0 : (w == 1) ? W1 : (w == 2) ? W2
                   : (w == 3) ? W3 : (w == 4) ? W4 : W5;
    float v = W[(size_t)k * Dq + n];
    __nv_bfloat16 h = __float2bfloat16_rn(v);
    __nv_bfloat16 l = __float2bfloat16_rn(v - __bfloat162float(h));
    __nv_bfloat16* basep = outb + (size_t)w * 32768;
    basep[n * 128 + k] = h;
    basep[16384 + n * 128 + k] = l;
}

// ---------------- E projection: E[m][k] = sum_d Wq[k][d]emb[m][d] + Wk[k][d]emb[m][128+d] ----
__global__ void eproj_kernel(const float* __restrict__ Wq, const float* __restrict__ Wk,
                             const float* __restrict__ bq, const float* __restrict__ bk,
                             const float* __restrict__ emb,
                             float* __restrict__ E, float* __restrict__ cvec)
{
    int i = blockIdx.x * 256 + threadIdx.x;   // 0..8191
    int m = i >> 7, k = i & 127;
    const float* em = emb + (size_t)m * 256;
    const float* wq = Wq + (size_t)k * Dq;
    const float* wk = Wk + (size_t)k * Dq;
    float s = 0.f;
#pragma unroll 8
    for (int d = 0; d < 128; d++)
        s += wq[d] * em[d] + wk[d] * em[128 + d];
    E[m * 128 + k] = s;
    if (k == 0) {
        float cc = 0.f;
#pragma unroll 8
        for (int d = 0; d < 128; d++)
            cc += em[d] * bq[d] + em[128 + d] * bk[d];
        cvec[m] = cc;
    }
}

// ================= mma.sync bf16 3-pass GEMM, K-split pipelined =========
// SMEM map (bytes):
#define SM2_BIAS 0           // 512B
#define SM2_MEAN 512         // 512B
#define SM2_RSTD 1024        // 512B
#define SM2_T    2048        // stage0 base; stage1 at +STAGE_BYTES
#define ROW2     144         // bf16 row stride bytes (64 bf16 + pad)
#define TILE_B   18432       // 128 * 144
#define STAGE_BYTES (4*TILE_B)   // AH, AL, BH, BL
#define GM2_SMEM_BYTES (2048 + 2*STAGE_BYTES)   // 149504

__device__ __forceinline__ void ldsm_x4(uint32_t* r, uint32_t addr) {
    asm volatile("ldmatrix.sync.aligned.m8n8.x4.shared.b16 {%0,%1,%2,%3}, [%4];"
        : "=r"(r[0]), "=r"(r[1]), "=r"(r[2]), "=r"(r[3]) : "r"(addr));
}
__device__ __forceinline__ void mma_bf16(float* d, const uint32_t* a, const uint32_t* b) {
    asm volatile("mma.sync.aligned.m16n8k16.row.col.f32.bf16.bf16.f32 "
        "{%0,%1,%2,%3}, {%4,%5,%6,%7}, {%8,%9}, {%0,%1,%2,%3};"
        : "+f"(d[0]), "+f"(d[1]), "+f"(d[2]), "+f"(d[3])
        : "r"(a[0]), "r"(a[1]), "r"(a[2]), "r"(a[3]), "r"(b[0]), "r"(b[1]));
}

__device__ __forceinline__ void split4_bf16(const float* f, uint2& hi, uint2& lo) {
    unsigned short h[4], l[4];
#pragma unroll
    for (int i = 0; i < 4; i++) {
        __nv_bfloat16 bh = __float2bfloat16_rn(f[i]);
        float fh = __bfloat162float(bh);
        __nv_bfloat16 bl = __float2bfloat16_rn(f[i] - fh);
        h[i] = __bfloat16_as_ushort(bh);
        l[i] = __bfloat16_as_ushort(bl);
    }
    hi = make_uint2((uint32_t)h[0] | ((uint32_t)h[1] << 16), (uint32_t)h[2] | ((uint32_t)h[3] << 16));
    lo = make_uint2((uint32_t)l[0] | ((uint32_t)l[1] << 16), (uint32_t)l[2] | ((uint32_t)l[3] << 16));
}

__device__ __forceinline__ void mma_stage(uint32_t SB, uint32_t a_row, uint32_t a_csel,
                                          uint32_t b_rowb, uint32_t b_csel,
                                          float (*acc)[8][4])
{
#pragma unroll
    for (int ks = 0; ks < 4; ks++) {
        uint32_t kb = (uint32_t)(ks * 32);
        uint32_t Ahf[2][4], Alf[2][4];
#pragma unroll
        for (int mi = 0; mi < 2; mi++) {
            uint32_t ad = SB + (a_row + mi * 16) * ROW2 + kb + a_csel;
            ldsm_x4(Ahf[mi], ad);
            ldsm_x4(Alf[mi], ad + TILE_B);
        }
        uint32_t Bhf[8][2], Blf[8][2];
#pragma unroll
        for (int np = 0; np < 4; np++) {
            uint32_t bd = SB + 2 * TILE_B + (b_rowb + np * 16) * ROW2 + kb + b_csel;
            uint32_t r[4];
            ldsm_x4(r, bd);
            Bhf[np*2][0] = r[0]; Bhf[np*2][1] = r[1];
            Bhf[np*2+1][0] = r[2]; Bhf[np*2+1][1] = r[3];
            ldsm_x4(r, bd + TILE_B);
            Blf[np*2][0] = r[0]; Blf[np*2][1] = r[1];
            Blf[np*2+1][0] = r[2]; Blf[np*2+1][1] = r[3];
        }
#pragma unroll
        for (int mi = 0; mi < 2; mi++)
#pragma unroll
            for (int ni = 0; ni < 8; ni++) {
                mma_bf16(acc[mi][ni], Ahf[mi], Bhf[ni]);
                mma_bf16(acc[mi][ni], Ahf[mi], Blf[ni]);
                mma_bf16(acc[mi][ni], Alf[mi], Bhf[ni]);
            }
    }
}

template<int EPI, bool ROWSCALE, bool POSADD, bool RESPOS>
__global__ __launch_bounds__(256) void gemm_mma(
    const float* __restrict__ A,
    const __nv_bfloat16* __restrict__ Bh_pre,
    const __nv_bfloat16* __restrict__ Bl_pre,
    const float* __restrict__ bias, const float* __restrict__ resid,
    const float* __restrict__ rowdiv, const float* __restrict__ pos,
    float* __restrict__ out)
{
    extern __shared__ char smem[];
    uint32_t sb = smem_u32(smem);
    int tid = threadIdx.x;
    int lane = tid & 31, wid = tid >> 5;
    int base = blockIdx.x * 128;

    if (tid < 128) ((float*)(smem + SM2_BIAS))[tid] = bias[tid];

    // ---- B tiles (both K-stages) via cp.async from precomputed bf16 split ----
#pragma unroll
    for (int s = 0; s < 2; s++) {
        uint32_t bbase = sb + SM2_T + s * STAGE_BYTES + 2 * TILE_B;
#pragma unroll
        for (int t = 0; t < 2; t++) {
            const __nv_bfloat16* src = t ? Bl_pre : Bh_pre;
#pragma unroll
            for (int p = 0; p < 4; p++) {
                int q = tid + p * 256;
                int row = q >> 3, c = q & 7;
                uint32_t sa = bbase + (uint32_t)(t * TILE_B + row * ROW2 + c * 16);
                const void* ga = src + row * 128 + s * 64 + c * 8;
                asm volatile("cp.async.cg.shared.global [%0], [%1], 16;" :: "r"(sa), "l"(ga));
            }
        }
        asm volatile("cp.async.commit_group;");
    }

    const float4* A4 = reinterpret_cast<const float4*>(A);
    const float4* pos4 = reinterpret_cast<const float4*>(pos);

    // ---- stage0 A: load + bf16 hi/lo convert + store ----
#pragma unroll
    for (int i = 0; i < 8; i++) {
        int f = tid + 256 * i;
        int row = f >> 4, c4 = f & 15;
        int grow = base + row;
        float4 v = A4[(size_t)grow * 32 + c4];
        if (POSADD) {
            float4 pv = pos4[(grow & (Nq - 1)) * 32 + c4];
            v.x += pv.x; v.y += pv.y; v.z += pv.z; v.w += pv.w;
        }
        if (ROWSCALE) {
            float rs = 1.0f / rowdiv[grow];
            v.x *= rs; v.y *= rs; v.z *= rs; v.w *= rs;
        }
        float ff[4] = {v.x, v.y, v.z, v.w};
        uint2 hi, lo; split4_bf16(ff, hi, lo);
        uint32_t off = (uint32_t)(SM2_T + row * ROW2 + c4 * 8);
        *reinterpret_cast<uint2*>(smem + off) = hi;
        *reinterpret_cast<uint2*>(smem + off + TILE_B) = lo;
    }
    asm volatile("cp.async.wait_group 1;");
    __syncthreads();

    // ---- prefetch stage1 A into registers (LDGs fly during stage0 MMA) ----
    float4 a1[8];
#pragma unroll
    for (int i = 0; i < 8; i++) {
        int f = tid + 256 * i;
        int row = f >> 4, c4 = f & 15;
        int grow = base + row;
        float4 v = A4[(size_t)grow * 32 + 16 + c4];
        if (POSADD) {
            float4 pv = pos4[(grow & (Nq - 1)) * 32 + 16 + c4];
            v.x += pv.x; v.y += pv.y; v.z += pv.z; v.w += pv.w;
        }
        if (ROWSCALE) {
            float rs = 1.0f / rowdiv[grow];
            v.x *= rs; v.y *= rs; v.z *= rs; v.w *= rs;
        }
        a1[i] = v;
    }

    int m0 = (wid & 3) * 32, n0 = (wid >> 2) * 64;
    uint32_t a_row  = (uint32_t)(m0 + (lane & 7) + ((lane >> 3) & 1) * 8);
    uint32_t a_csel = (uint32_t)((lane >> 4) * 16);
    uint32_t b_rowb = (uint32_t)(n0 + (lane & 7) + (lane >> 4) * 8);
    uint32_t b_csel = (uint32_t)(((lane >> 3) & 1) * 16);

    float acc[2][8][4];
#pragma unroll
    for (int mi = 0; mi < 2; mi++)
#pragma unroll
        for (int ni = 0; ni < 8; ni++)
#pragma unroll
            for (int c = 0; c < 4; c++) acc[mi][ni][c] = 0.f;

    mma_stage(sb + SM2_T, a_row, a_csel, b_rowb, b_csel, acc);

    // ---- convert + store stage1 A ----
#pragma unroll
    for (int i = 0; i < 8; i++) {
        int f = tid + 256 * i;
        int row = f >> 4, c4 = f & 15;
        float ff[4] = {a1[i].x, a1[i].y, a1[i].z, a1[i].w};
        uint2 hi, lo; split4_bf16(ff, hi, lo);
        uint32_t off = (uint32_t)(SM2_T + STAGE_BYTES + row * ROW2 + c4 * 8);
        *reinterpret_cast<uint2*>(smem + off) = hi;
        *reinterpret_cast<uint2*>(smem + off + TILE_B) = lo;
    }
    asm volatile("cp.async.wait_group 0;");
    __syncthreads();

    mma_stage(sb + SM2_T + STAGE_BYTES, a_row, a_csel, b_rowb, b_csel, acc);

    __syncthreads();

    // ---- stage D in SMEM (f32, stride 132 floats, overlays stage0) ----
    {
        float* Ds = (float*)(smem + SM2_T);
        int dr = lane >> 2, dc = (lane & 3) * 2;
#pragma unroll
        for (int mi = 0; mi < 2; mi++)
#pragma unroll
            for (int ni = 0; ni < 8; ni++) {
                int m = m0 + mi * 16 + dr, n = n0 + ni * 8 + dc;
                *reinterpret_cast<float2*>(&Ds[m * 132 + n]) =
                    make_float2(acc[mi][ni][0], acc[mi][ni][1]);
                *reinterpret_cast<float2*>(&Ds[(m + 8) * 132 + n]) =
                    make_float2(acc[mi][ni][2], acc[mi][ni][3]);
            }
    }
    __syncthreads();

    float4* ds4 = (float4*)(smem + SM2_T);
    const float4* bias4 = (const float4*)(smem + SM2_BIAS);
    float4* out4 = (float4*)out;

    if (EPI == EPI_LN) {
        const float4* resid4 = (const float4*)resid;
#pragma unroll
        for (int i = 0; i < 16; i++) {
            int f = tid + 256 * i;
            int row = f >> 5, c4 = f & 31;
            float4 d = ds4[row * 33 + c4];
            float4 b = bias4[c4];
            float4 rr = resid4[(size_t)(base + row) * 32 + c4];
            if (RESPOS) {
                float4 pv = pos4[((base + row) & (Nq - 1)) * 32 + c4];
                rr.x += pv.x; rr.y += pv.y; rr.z += pv.z; rr.w += pv.w;
            }
            d.x += b.x + rr.x; d.y += b.y + rr.y;
            d.z += b.z + rr.z; d.w += b.w + rr.w;
            ds4[row * 33 + c4] = d;
        }
        __syncthreads();
        if (tid < 128) {
            const float* Ds = (const float*)(smem + SM2_T);
            float s = 0.f;
#pragma unroll 8
            for (int c = 0; c < 128; c++) s += Ds[tid * 132 + c];
            float mean = s * (1.0f / 128.0f);
            float sq = 0.f;
#pragma unroll 8
            for (int c = 0; c < 128; c++) {
                float dv = Ds[tid * 132 + c] - mean;
                sq += dv * dv;
            }
            ((float*)(smem + SM2_MEAN))[tid] = mean;
            ((float*)(smem + SM2_RSTD))[tid] = rsqrtf(sq * (1.0f / 128.0f) + 1e-5f);
        }
        __syncthreads();
        const float* meanS = (const float*)(smem + SM2_MEAN);
        const float* rstdS = (const float*)(smem + SM2_RSTD);
#pragma unroll
        for (int i = 0; i < 16; i++) {
            int f = tid + 256 * i;
            int row = f >> 5, c4 = f & 31;
            float4 d = ds4[row * 33 + c4];
            float mn = meanS[row], rs = rstdS[row];
            d.x = (d.x - mn) * rs; d.y = (d.y - mn) * rs;
            d.z = (d.z - mn) * rs; d.w = (d.w - mn) * rs;
            out4[(size_t)(base + row) * 32 + c4] = d;
        }
    } else {
#pragma unroll
        for (int i = 0; i < 16; i++) {
            int f = tid + 256 * i;
            int row = f >> 5, c4 = f & 31;
            float4 d = ds4[row * 33 + c4];
            float4 b = bias4[c4];
            d.x += b.x; d.y += b.y; d.z += b.z; d.w += b.w;
            if (EPI == EPI_RELU) {
                d.x = fmaxf(d.x, 0.f); d.y = fmaxf(d.y, 0.f);
                d.z = fmaxf(d.z, 0.f); d.w = fmaxf(d.w, 0.f);
            }
            out4[(size_t)(base + row) * 32 + c4] = d;
        }
    }
}

// ---------------- logits: L[bt][m][n] = (x+pos)[bt,n,:]·E[m,:] + c[m] ----------------
// Register-blocked fp32 GEMM: block tile 128n x 64m, thread tile 8n x 4m,
// all compute loads are conflict-free LDS.128.
__global__ __launch_bounds__(256) void logits_kernel(
    const float* __restrict__ xg, const float* __restrict__ pos,
    const float* __restrict__ E, const float* __restrict__ cvec,
    float* __restrict__ logits)
{
    __shared__ float Es[32][68];    // k x m (64 + pad)
    __shared__ float Fs[32][132];   // k x n (128 + pad)
    int tid = threadIdx.x;
    int bt = blockIdx.y;
    int n0 = blockIdx.x * 128;
    int ng = tid & 15;    // n-sub * 8
    int mg = tid >> 4;    // m-sub * 4

    float acc[8][4];
#pragma unroll
    for (int a = 0; a < 8; a++)
#pragma unroll
        for (int b = 0; b < 4; b++) acc[a][b] = 0.f;

    for (int kc = 0; kc < 4; kc++) {
        int k0 = kc * 32;
        // Es fill: 32k x 64m = 512 float4 reads (2/thread), transposed store
#pragma unroll
        for (int p = 0; p < 2; p++) {
            int q = tid + p * 256;          // 0..511
            int m = q >> 3, c4 = q & 7;
            float4 v = *reinterpret_cast<const float4*>(&E[m * 128 + k0 + c4 * 4]);
            Es[c4 * 4 + 0][m] = v.x;
            Es[c4 * 4 + 1][m] = v.y;
            Es[c4 * 4 + 2][m] = v.z;
            Es[c4 * 4 + 3][m] = v.w;
        }
        // Fs fill: 32k x 128n = 1024 float4 reads (4/thread), transposed store
#pragma unroll
        for (int p = 0; p < 4; p++) {
            int q = tid + p * 256;          // 0..1023
            int n = q >> 3, c4 = q & 7;
            int gn = n0 + n;
            float4 xv = *reinterpret_cast<const float4*>(
                &xg[(size_t)(bt * Nq + gn) * Dq + k0 + c4 * 4]);
            float4 pv = *reinterpret_cast<const float4*>(&pos[gn * Dq + k0 + c4 * 4]);
            Fs[c4 * 4 + 0][n] = xv.x + pv.x;
            Fs[c4 * 4 + 1][n] = xv.y + pv.y;
            Fs[c4 * 4 + 2][n] = xv.z + pv.z;
            Fs[c4 * 4 + 3][n] = xv.w + pv.w;
        }
        __syncthreads();
#pragma unroll
        for (int k = 0; k < 32; k++) {
            float4 em = *reinterpret_cast<const float4*>(&Es[k][mg * 4]);
            float4 fa = *reinterpret_cast<const float4*>(&Fs[k][ng * 8]);
            float4 fb = *reinterpret_cast<const float4*>(&Fs[k][ng * 8 + 4]);
            float f[8] = {fa.x, fa.y, fa.z, fa.w, fb.x, fb.y, fb.z, fb.w};
            float e[4] = {em.x, em.y, em.z, em.w};
#pragma unroll
            for (int a = 0; a < 8; a++)
#pragma unroll
                for (int b = 0; b < 4; b++) acc[a][b] += f[a] * e[b];
        }
        __syncthreads();
    }
    // write: rows m = mg*4+mm, cols n0 + ng*8 .. +7
#pragma unroll
    for (int mm = 0; mm < 4; mm++) {
        float cm = cvec[mg * 4 + mm];
        size_t basei = (size_t)bt * (Mq * Nq) + (size_t)(mg * 4 + mm) * Nq + n0 + ng * 8;
        float4 o0 = make_float4(acc[0][mm] + cm, acc[1][mm] + cm, acc[2][mm] + cm, acc[3][mm] + cm);
        float4 o1 = make_float4(acc[4][mm] + cm, acc[5][mm] + cm, acc[6][mm] + cm, acc[7][mm] + cm);
        *reinterpret_cast<float4*>(&logits[basei]) = o0;
        *reinterpret_cast<float4*>(&logits[basei + 4]) = o1;
    }
}

// ---------------- top-16 per row (warp per row, lowest-index tie-break) ----------------
__global__ __launch_bounds__(256) void topk_kernel(const float* __restrict__ logits,
                                                   int* __restrict__ idxout)
{
    int row = blockIdx.x * 8 + (threadIdx.x >> 5);
    int lane = threadIdx.x & 31;
    const float* p = logits + (size_t)row * Nq;
    float v[32];
#pragma unroll
    for (int q = 0; q < 32; q++) v[q] = p[q * 32 + lane];

    for (int t = 0; t < TOPKq; t++) {
        float bvv = v[0]; int bq = 0;
#pragma unroll
        for (int q = 1; q < 32; q++)
            if (v[q] > bvv) { bvv = v[q]; bq = q; }
        int bi = bq * 32 + lane;
#pragma unroll
        for (int o = 16; o > 0; o >>= 1) {
            float ov = __shfl_xor_sync(0xffffffffu, bvv, o);
            int   oi = __shfl_xor_sync(0xffffffffu, bi, o);
            if (ov > bvv || (ov == bvv && oi < bi)) { bvv = ov; bi = oi; }
        }
        if (lane == 0) idxout[row * TOPKq + t] = bi;
#pragma unroll
        for (int q = 0; q < 32; q++)
            if (q * 32 + lane == bi) v[q] = -INFINITY;
    }
}

// ---------------- init dict / counts ----------------
__global__ void init_kernel(float* __restrict__ dict, float* __restrict__ counts)
{
    int i = blockIdx.x * blockDim.x + threadIdx.x;
    if (i < (int)(BTND / 4))
        reinterpret_cast<float4*>(dict)[i] = make_float4(0.f, 0.f, 0.f, 0.f);
    if (i < BTN) counts[i] = 1e-14f;
}

// ---------------- fused gather + 16x16 attention + scatter-add ----------------
__global__ __launch_bounds__(256) void attn_kernel(
    const float* __restrict__ Qg, const float* __restrict__ Kg,
    const float* __restrict__ Vg, const int* __restrict__ idxin,
    float* __restrict__ dict, float* __restrict__ counts)
{
    __shared__ int sidx[16];
    __shared__ float Qs[16][132], Ks[16][132], Vs[16][132];
    __shared__ float Sa[16][16];
    int tid = threadIdx.x;
    int bx = blockIdx.x;            // bt*64 + m
    int bt = bx >> 6;

    if (tid < 16) sidx[tid] = idxin[bx * TOPKq + tid];
    __syncthreads();
#pragma unroll
    for (int p = 0; p < 8; p++) {
        int q = tid + p * 256;
        int k = q >> 7, d = q & 127;
        size_t src = (size_t)(bt * Nq + sidx[k]) * Dq + d;
        Qs[k][d] = Qg[src];
        Ks[k][d] = Kg[src];
        Vs[k][d] = Vg[src];
    }
    __syncthreads();
    {
        int k = tid >> 4, j = tid & 15;
        float s = 0.f;
#pragma unroll 8
        for (int d = 0; d < 128; d++) s += Qs[k][d] * Ks[j][d];
        s *= 0.08838834764831845f;   // 1/sqrt(128)
        float mx = s;
#pragma unroll
        for (int o = 8; o > 0; o >>= 1)
            mx = fmaxf(mx, __shfl_xor_sync(0xffffffffu, mx, o, 16));
        float e = expf(s - mx);
        float sm = e;
#pragma unroll
        for (int o = 8; o > 0; o >>= 1)
            sm += __shfl_xor_sync(0xffffffffu, sm, o, 16);
        Sa[k][j] = e / sm;
    }
    __syncthreads();
#pragma unroll
    for (int p = 0; p < 8; p++) {
        int q = tid + p * 256;
        int k = q >> 7, d = q & 127;
        float v = 0.f;
#pragma unroll
        for (int j = 0; j < 16; j++) v += Sa[k][j] * Vs[j][d];
        atomicAdd(&dict[(size_t)(bt * Nq + sidx[k]) * Dq + d], v);
    }
    if (tid < 16) atomicAdd(&counts[bt * Nq + sidx[tid]], 1.0f);
}

// ---------------- launcher ----------------
extern "C" void kernel_launch(void* const* d_in, const int* in_sizes, int n_in,
                              void* d_out, int out_size)
{
    const float* x       = (const float*)d_in[0];
    const float* eigvec  = (const float*)d_in[1];
    const float* eigval  = (const float*)d_in[2];
    const float* Wq_     = (const float*)d_in[3];
    const float* bq_     = (const float*)d_in[4];
    const float* Wk_     = (const float*)d_in[5];
    const float* bk_     = (const float*)d_in[6];
    const float* Wv_     = (const float*)d_in[7];
    const float* bv_     = (const float*)d_in[8];
    const float* Wo_     = (const float*)d_in[9];
    const float* bo_     = (const float*)d_in[10];
    const float* nodeemb = (const float*)d_in[11];
    const float* ffW1    = (const float*)d_in[12];
    const float* ffb1    = (const float*)d_in[13];
    const float* ffW2    = (const float*)d_in[14];
    const float* ffb2    = (const float*)d_in[15];
    // d_in[16] = adj (unused by the reference computation)
    float* out = (float*)d_out;

    float* S = nullptr;
    cudaGetSymbolAddress((void**)&S, g_scratch);
    float* Qp    = S + OFF_Q;
    float* Kp    = S + OFF_K;
    float* Vp    = S + OFF_V;
    float* dict  = S + OFF_DICT;
    float* val   = S + OFF_VAL;
    float* ff1   = S + OFF_FF1;
    float* logit = S + OFF_LOG;
    float* cnt   = S + OFF_CNT;
    int*   idx   = (int*)(S + OFF_IDX);
    float* posp  = S + OFF_POS;
    float* Ep    = S + OFF_E;
    float* cp    = S + OFF_C;
    __nv_bfloat16* wbf = (__nv_bfloat16*)(S + OFF_WBF);
    // weight slots: 0=Wq, 1=Wk, 2=Wv, 3=Wo, 4=ffW1, 5=ffW2
#define WBH(w) (wbf + (size_t)(w) * 32768)
#define WBL(w) (wbf + (size_t)(w) * 32768 + 16384)

    cudaFuncSetAttribute(gemm_mma<EPI_BIAS, false, true,  false>, cudaFuncAttributeMaxDynamicSharedMemorySize, GM2_SMEM_BYTES);
    cudaFuncSetAttribute(gemm_mma<EPI_LN,   true,  false, true >, cudaFuncAttributeMaxDynamicSharedMemorySize, GM2_SMEM_BYTES);
    cudaFuncSetAttribute(gemm_mma<EPI_RELU, false, false, false>, cudaFuncAttributeMaxDynamicSharedMemorySize, GM2_SMEM_BYTES);
    cudaFuncSetAttribute(gemm_mma<EPI_LN,   false, false, false>, cudaFuncAttributeMaxDynamicSharedMemorySize, GM2_SMEM_BYTES);

    // 0. precompute pos, W bf16 splits, E/c projection (tiny)
    pos_kernel<<<512, 256>>>(eigvec, eigval, posp);
    wsplit_kernel<<<384, 256>>>(Wq_, Wk_, Wv_, Wo_, ffW1, ffW2, wbf);
    eproj_kernel<<<32, 256>>>(Wq_, Wk_, bq_, bk_, nodeemb, Ep, cp);

    // 1. node-selection logits via restructured form (no Q/K dependency)
    logits_kernel<<<dim3(Nq / 128, BT), 256>>>(x, posp, Ep, cp, logit);

    // 2. top-16 per (bt, m)
    topk_kernel<<<NROWS / 8, 256>>>(logit, idx);

    // 3. Q,K,V via pipelined HMMA (smooth paths only now)
    const int GT = BTN / 128;   // 1536
    gemm_mma<EPI_BIAS, false, true, false><<<GT, 256, GM2_SMEM_BYTES>>>(
        x, WBH(0), WBL(0), bq_, nullptr, nullptr, posp, Qp);
    gemm_mma<EPI_BIAS, false, true, false><<<GT, 256, GM2_SMEM_BYTES>>>(
        x, WBH(1), WBL(1), bk_, nullptr, nullptr, posp, Kp);
    gemm_mma<EPI_BIAS, false, true, false><<<GT, 256, GM2_SMEM_BYTES>>>(
        x, WBH(2), WBL(2), bv_, nullptr, nullptr, posp, Vp);

    // 4. init scatter buffers
    init_kernel<<<(int)(BTND / 4 / 256), 256>>>(dict, cnt);

    // 5. gather + local attention + scatter-add
    attn_kernel<<<NROWS, 256>>>(Qp, Kp, Vp, idx, dict, cnt);

    // 6. value = LN((dict/counts) @ Wo + bo + (x + pos))
    gemm_mma<EPI_LN, true, false, true><<<GT, 256, GM2_SMEM_BYTES>>>(
        dict, WBH(3), WBL(3), bo_, x, cnt, posp, val);

    // 7. FFN
    gemm_mma<EPI_RELU, false, false, false><<<GT, 256, GM2_SMEM_BYTES>>>(
        val, WBH(4), WBL(4), ffb1, nullptr, nullptr, posp, ff1);
    gemm_mma<EPI_LN, false, false, false><<<GT, 256, GM2_SMEM_BYTES>>>(
        ff1, WBH(5), WBL(5), ffb2, val, nullptr, posp, out);
}

// round 16
// speedup vs baseline: 1.4608x; 1.4608x over previous
#include <cuda_runtime.h>
#include <cuda_bf16.h>
#include <math.h>
#include <stdint.h>

// ---------------- problem constants ----------------
#define Bq 16
#define Tq 12
#define Nq 1024
#define Dq 128
#define Mq 64
#define TOPKq 16

#define BT (Bq*Tq)                  // 192
#define BTN (BT*Nq)                 // 196608
#define BTND ((size_t)BTN*Dq)       // 25165824
#define NROWS (BT*Mq)               // 12288 topk rows

// ---------------- scratch layout (floats) ----------------
#define OFF_Q    ((size_t)25165824*1)
#define OFF_K    ((size_t)25165824*2)
#define OFF_V    ((size_t)25165824*3)
#define OFF_DICT ((size_t)25165824*4)
#define OFF_VAL  ((size_t)25165824*5)
#define OFF_FF1  ((size_t)25165824*6)
#define OFF_LOG  ((size_t)25165824*7)               // 192*64*1024 = 12582912
#define OFF_CNT  (OFF_LOG + (size_t)12582912)       // 196608
#define OFF_IDX  (OFF_CNT + (size_t)196608)         // 196608 ints
#define OFF_POS  (OFF_IDX + (size_t)196608)         // 131072 floats (pos[n][d])
#define OFF_WBF  (OFF_POS + (size_t)131072)         // 98304 floats = 196608 bf16 (6 weights)
#define OFF_E    (OFF_WBF + (size_t)98304)          // 8192 floats  E[m][k]
#define OFF_C    (OFF_E   + (size_t)8192)           // 64 floats    c[m]
#define TOTAL_SCRATCH (OFF_C + (size_t)64)

__device__ float g_scratch[TOTAL_SCRATCH];

__device__ __forceinline__ uint32_t smem_u32(const void* p) {
    uint32_t a;
    asm("{ .reg .u64 t; cvta.to.shared.u64 t, %1; cvt.u32.u64 %0, t; }" : "=r"(a) : "l"(p));
    return a;
}

enum { EPI_BIAS = 0, EPI_RELU = 1, EPI_LN = 2 };

// ---------------- pos precompute: pos[n][d] = eigvec[d][n] * eigval[d] ----------------
__global__ void pos_kernel(const float* __restrict__ eigvec,
                           const float* __restrict__ eigval,
                           float* __restrict__ posout)
{
    int i = blockIdx.x * 256 + threadIdx.x;   // 0..131071
    int d = i >> 10, n = i & 1023;
    posout[n * Dq + d] = eigvec[(size_t)d * Nq + n] * eigval[d];
}

// ---------------- W bf16 hi/lo split precompute (B = W^T layout [n][k]) ----------------
__global__ void wsplit_kernel(const float* __restrict__ W0, const float* __restrict__ W1,
                              const float* __restrict__ W2, const float* __restrict__ W3,
                              const float* __restrict__ W4, const float* __restrict__ W5,
                              __nv_bfloat16* __restrict__ outb)
{
    int g = blockIdx.x * 256 + threadIdx.x;   // 0..98303
    int w = g >> 14;
    int i = g & 16383;
    int n = i & 127, k = i >> 7;
    const float* W = (w == 0) ? W0 : (w == 1) ? W1 : (w == 2) ? W2
                   : (w == 3) ? W3 : (w == 4) ? W4 : W5;
    float v = W[(size_t)k * Dq + n];
    __nv_bfloat16 h = __float2bfloat16_rn(v);
    __nv_bfloat16 l = __float2bfloat16_rn(v - __bfloat162float(h));
    __nv_bfloat16* basep = outb + (size_t)w * 32768;
    basep[n * 128 + k] = h;
    basep[16384 + n * 128 + k] = l;
}

// ---------------- E projection: E[m][k] = sum_d Wq[k][d]emb[m][d] + Wk[k][d]emb[m][128+d] ----
__global__ void eproj_kernel(const float* __restrict__ Wq, const float* __restrict__ Wk,
                             const float* __restrict__ bq, const float* __restrict__ bk,
                             const float* __restrict__ emb,
                             float* __restrict__ E, float* __restrict__ cvec)
{
    int i = blockIdx.x * 256 + threadIdx.x;   // 0..8191
    int m = i >> 7, k = i & 127;
    const float* em = emb + (size_t)m * 256;
    const float* wq = Wq + (size_t)k * Dq;
    const float* wk = Wk + (size_t)k * Dq;
    float s = 0.f;
#pragma unroll 8
    for (int d = 0; d < 128; d++)
        s += wq[d] * em[d] + wk[d] * em[128 + d];
    E[m * 128 + k] = s;
    if (k == 0) {
        float cc = 0.f;
#pragma unroll 8
        for (int d = 0; d < 128; d++)
            cc += em[d] * bq[d] + em[128 + d] * bk[d];
        cvec[m] = cc;
    }
}

// ================= mma.sync bf16 3-pass GEMM, K-split pipelined =========
// SMEM map (bytes):
#define SM2_BIAS 0           // 512B
#define SM2_MEAN 512         // 512B
#define SM2_RSTD 1024        // 512B
#define SM2_T    2048        // stage0 base; stage1 at +STAGE_BYTES
#define ROW2     144         // bf16 row stride bytes (64 bf16 + pad)
#define TILE_B   18432       // 128 * 144
#define STAGE_BYTES (4*TILE_B)   // AH, AL, BH, BL
#define GM2_SMEM_BYTES (2048 + 2*STAGE_BYTES)   // 149504

__device__ __forceinline__ void ldsm_x4(uint32_t* r, uint32_t addr) {
    asm volatile("ldmatrix.sync.aligned.m8n8.x4.shared.b16 {%0,%1,%2,%3}, [%4];"
        : "=r"(r[0]), "=r"(r[1]), "=r"(r[2]), "=r"(r[3]) : "r"(addr));
}
__device__ __forceinline__ void mma_bf16(float* d, const uint32_t* a, const uint32_t* b) {
    asm volatile("mma.sync.aligned.m16n8k16.row.col.f32.bf16.bf16.f32 "
        "{%0,%1,%2,%3}, {%4,%5,%6,%7}, {%8,%9}, {%0,%1,%2,%3};"
        : "+f"(d[0]), "+f"(d[1]), "+f"(d[2]), "+f"(d[3])
        : "r"(a[0]), "r"(a[1]), "r"(a[2]), "r"(a[3]), "r"(b[0]), "r"(b[1]));
}

__device__ __forceinline__ void split4_bf16(const float* f, uint2& hi, uint2& lo) {
    unsigned short h[4], l[4];
#pragma unroll
    for (int i = 0; i < 4; i++) {
        __nv_bfloat16 bh = __float2bfloat16_rn(f[i]);
        float fh = __bfloat162float(bh);
        __nv_bfloat16 bl = __float2bfloat16_rn(f[i] - fh);
        h[i] = __bfloat16_as_ushort(bh);
        l[i] = __bfloat16_as_ushort(bl);
    }
    hi = make_uint2((uint32_t)h[0] | ((uint32_t)h[1] << 16), (uint32_t)h[2] | ((uint32_t)h[3] << 16));
    lo = make_uint2((uint32_t)l[0] | ((uint32_t)l[1] << 16), (uint32_t)l[2] | ((uint32_t)l[3] << 16));
}

__device__ __forceinline__ void mma_stage(uint32_t SB, uint32_t a_row, uint32_t a_csel,
                                          uint32_t b_rowb, uint32_t b_csel,
                                          float (*acc)[8][4])
{
#pragma unroll
    for (int ks = 0; ks < 4; ks++) {
        uint32_t kb = (uint32_t)(ks * 32);
        uint32_t Ahf[2][4], Alf[2][4];
#pragma unroll
        for (int mi = 0; mi < 2; mi++) {
            uint32_t ad = SB + (a_row + mi * 16) * ROW2 + kb + a_csel;
            ldsm_x4(Ahf[mi], ad);
            ldsm_x4(Alf[mi], ad + TILE_B);
        }
        uint32_t Bhf[8][2], Blf[8][2];
#pragma unroll
        for (int np = 0; np < 4; np++) {
            uint32_t bd = SB + 2 * TILE_B + (b_rowb + np * 16) * ROW2 + kb + b_csel;
            uint32_t r[4];
            ldsm_x4(r, bd);
            Bhf[np*2][0] = r[0]; Bhf[np*2][1] = r[1];
            Bhf[np*2+1][0] = r[2]; Bhf[np*2+1][1] = r[3];
            ldsm_x4(r, bd + TILE_B);
            Blf[np*2][0] = r[0]; Blf[np*2][1] = r[1];
            Blf[np*2+1][0] = r[2]; Blf[np*2+1][1] = r[3];
        }
#pragma unroll
        for (int mi = 0; mi < 2; mi++)
#pragma unroll
            for (int ni = 0; ni < 8; ni++) {
                mma_bf16(acc[mi][ni], Ahf[mi], Bhf[ni]);
                mma_bf16(acc[mi][ni], Ahf[mi], Blf[ni]);
                mma_bf16(acc[mi][ni], Alf[mi], Bhf[ni]);
            }
    }
}

template<int EPI, bool ROWSCALE, bool POSADD, bool RESPOS>
__global__ __launch_bounds__(256) void gemm_mma(
    const float* __restrict__ A,
    const __nv_bfloat16* __restrict__ Bh_pre,
    const __nv_bfloat16* __restrict__ Bl_pre,
    const float* __restrict__ bias, const float* __restrict__ resid,
    const float* __restrict__ rowdiv, const float* __restrict__ pos,
    float* __restrict__ out)
{
    extern __shared__ char smem[];
    uint32_t sb = smem_u32(smem);
    int tid = threadIdx.x;
    int lane = tid & 31, wid = tid >> 5;
    int base = blockIdx.x * 128;

    if (tid < 128) ((float*)(smem + SM2_BIAS))[tid] = bias[tid];

    // ---- B tiles (both K-stages) via cp.async from precomputed bf16 split ----
#pragma unroll
    for (int s = 0; s < 2; s++) {
        uint32_t bbase = sb + SM2_T + s * STAGE_BYTES + 2 * TILE_B;
#pragma unroll
        for (int t = 0; t < 2; t++) {
            const __nv_bfloat16* src = t ? Bl_pre : Bh_pre;
#pragma unroll
            for (int p = 0; p < 4; p++) {
                int q = tid + p * 256;
                int row = q >> 3, c = q & 7;
                uint32_t sa = bbase + (uint32_t)(t * TILE_B + row * ROW2 + c * 16);
                const void* ga = src + row * 128 + s * 64 + c * 8;
                asm volatile("cp.async.cg.shared.global [%0], [%1], 16;" :: "r"(sa), "l"(ga));
            }
        }
        asm volatile("cp.async.commit_group;");
    }

    const float4* A4 = reinterpret_cast<const float4*>(A);
    const float4* pos4 = reinterpret_cast<const float4*>(pos);

    // ---- stage0 A: load + bf16 hi/lo convert + store ----
#pragma unroll
    for (int i = 0; i < 8; i++) {
        int f = tid + 256 * i;
        int row = f >> 4, c4 = f & 15;
        int grow = base + row;
        float4 v = A4[(size_t)grow * 32 + c4];
        if (POSADD) {
            float4 pv = pos4[(grow & (Nq - 1)) * 32 + c4];
            v.x += pv.x; v.y += pv.y; v.z += pv.z; v.w += pv.w;
        }
        if (ROWSCALE) {
            float rs = 1.0f / rowdiv[grow];
            v.x *= rs; v.y *= rs; v.z *= rs; v.w *= rs;
        }
        float ff[4] = {v.x, v.y, v.z, v.w};
        uint2 hi, lo; split4_bf16(ff, hi, lo);
        uint32_t off = (uint32_t)(SM2_T + row * ROW2 + c4 * 8);
        *reinterpret_cast<uint2*>(smem + off) = hi;
        *reinterpret_cast<uint2*>(smem + off + TILE_B) = lo;
    }
    asm volatile("cp.async.wait_group 1;");
    __syncthreads();

    // ---- prefetch stage1 A into registers (LDGs fly during stage0 MMA) ----
    float4 a1[8];
#pragma unroll
    for (int i = 0; i < 8; i++) {
        int f = tid + 256 * i;
        int row = f >> 4, c4 = f & 15;
        int grow = base + row;
        float4 v = A4[(size_t)grow * 32 + 16 + c4];
        if (POSADD) {
            float4 pv = pos4[(grow & (Nq - 1)) * 32 + 16 + c4];
            v.x += pv.x; v.y += pv.y; v.z += pv.z; v.w += pv.w;
        }
        if (ROWSCALE) {
            float rs = 1.0f / rowdiv[grow];
            v.x *= rs; v.y *= rs; v.z *= rs; v.w *= rs;
        }
        a1[i] = v;
    }

    int m0 = (wid & 3) * 32, n0 = (wid >> 2) * 64;
    uint32_t a_row  = (uint32_t)(m0 + (lane & 7) + ((lane >> 3) & 1) * 8);
    uint32_t a_csel = (uint32_t)((lane >> 4) * 16);
    uint32_t b_rowb = (uint32_t)(n0 + (lane & 7) + (lane >> 4) * 8);
    uint32_t b_csel = (uint32_t)(((lane >> 3) & 1) * 16);

    float acc[2][8][4];
#pragma unroll
    for (int mi = 0; mi < 2; mi++)
#pragma unroll
        for (int ni = 0; ni < 8; ni++)
#pragma unroll
            for (int c = 0; c < 4; c++) acc[mi][ni][c] = 0.f;

    mma_stage(sb + SM2_T, a_row, a_csel, b_rowb, b_csel, acc);

    // ---- convert + store stage1 A ----
#pragma unroll
    for (int i = 0; i < 8; i++) {
        int f = tid + 256 * i;
        int row = f >> 4, c4 = f & 15;
        float ff[4] = {a1[i].x, a1[i].y, a1[i].z, a1[i].w};
        uint2 hi, lo; split4_bf16(ff, hi, lo);
        uint32_t off = (uint32_t)(SM2_T + STAGE_BYTES + row * ROW2 + c4 * 8);
        *reinterpret_cast<uint2*>(smem + off) = hi;
        *reinterpret_cast<uint2*>(smem + off + TILE_B) = lo;
    }
    asm volatile("cp.async.wait_group 0;");
    __syncthreads();

    mma_stage(sb + SM2_T + STAGE_BYTES, a_row, a_csel, b_rowb, b_csel, acc);

    __syncthreads();

    // ---- stage D in SMEM (f32, stride 132 floats, overlays stage0) ----
    {
        float* Ds = (float*)(smem + SM2_T);
        int dr = lane >> 2, dc = (lane & 3) * 2;
#pragma unroll
        for (int mi = 0; mi < 2; mi++)
#pragma unroll
            for (int ni = 0; ni < 8; ni++) {
                int m = m0 + mi * 16 + dr, n = n0 + ni * 8 + dc;
                *reinterpret_cast<float2*>(&Ds[m * 132 + n]) =
                    make_float2(acc[mi][ni][0], acc[mi][ni][1]);
                *reinterpret_cast<float2*>(&Ds[(m + 8) * 132 + n]) =
                    make_float2(acc[mi][ni][2], acc[mi][ni][3]);
            }
    }
    __syncthreads();

    float4* ds4 = (float4*)(smem + SM2_T);
    const float4* bias4 = (const float4*)(smem + SM2_BIAS);
    float4* out4 = (float4*)out;

    if (EPI == EPI_LN) {
        const float4* resid4 = (const float4*)resid;
#pragma unroll
        for (int i = 0; i < 16; i++) {
            int f = tid + 256 * i;
            int row = f >> 5, c4 = f & 31;
            float4 d = ds4[row * 33 + c4];
            float4 b = bias4[c4];
            float4 rr = resid4[(size_t)(base + row) * 32 + c4];
            if (RESPOS) {
                float4 pv = pos4[((base + row) & (Nq - 1)) * 32 + c4];
                rr.x += pv.x; rr.y += pv.y; rr.z += pv.z; rr.w += pv.w;
            }
            d.x += b.x + rr.x; d.y += b.y + rr.y;
            d.z += b.z + rr.z; d.w += b.w + rr.w;
            ds4[row * 33 + c4] = d;
        }
        __syncthreads();
        if (tid < 128) {
            const float* Ds = (const float*)(smem + SM2_T);
            float s = 0.f;
#pragma unroll 8
            for (int c = 0; c < 128; c++) s += Ds[tid * 132 + c];
            float mean = s * (1.0f / 128.0f);
            float sq = 0.f;
#pragma unroll 8
            for (int c = 0; c < 128; c++) {
                float dv = Ds[tid * 132 + c] - mean;
                sq += dv * dv;
            }
            ((float*)(smem + SM2_MEAN))[tid] = mean;
            ((float*)(smem + SM2_RSTD))[tid] = rsqrtf(sq * (1.0f / 128.0f) + 1e-5f);
        }
        __syncthreads();
        const float* meanS = (const float*)(smem + SM2_MEAN);
        const float* rstdS = (const float*)(smem + SM2_RSTD);
#pragma unroll
        for (int i = 0; i < 16; i++) {
            int f = tid + 256 * i;
            int row = f >> 5, c4 = f & 31;
            float4 d = ds4[row * 33 + c4];
            float mn = meanS[row], rs = rstdS[row];
            d.x = (d.x - mn) * rs; d.y = (d.y - mn) * rs;
            d.z = (d.z - mn) * rs; d.w = (d.w - mn) * rs;
            out4[(size_t)(base + row) * 32 + c4] = d;
        }
    } else {
#pragma unroll
        for (int i = 0; i < 16; i++) {
            int f = tid + 256 * i;
            int row = f >> 5, c4 = f & 31;
            float4 d = ds4[row * 33 + c4];
            float4 b = bias4[c4];
            d.x += b.x; d.y += b.y; d.z += b.z; d.w += b.w;
            if (EPI == EPI_RELU) {
                d.x = fmaxf(d.x, 0.f); d.y = fmaxf(d.y, 0.f);
                d.z = fmaxf(d.z, 0.f); d.w = fmaxf(d.w, 0.f);
            }
            out4[(size_t)(base + row) * 32 + c4] = d;
        }
    }
}

// ---------------- logits: L[bt][m][n] = (x+pos)[bt,n,:]·E[m,:] + c[m] ----------------
// Round-14 structure (64x64 tile), pad 65->68 so compute uses conflict-free LDS.128.
__global__ __launch_bounds__(256) void logits_kernel(
    const float* __restrict__ xg, const float* __restrict__ pos,
    const float* __restrict__ E, const float* __restrict__ cvec,
    float* __restrict__ logits)
{
    __shared__ float Es[64][68];   // k-chunk x m (16B-aligned rows)
    __shared__ float Fs[64][68];   // k-chunk x n
    int tid = threadIdx.x;
    int bt = blockIdx.y;
    int n0 = blockIdx.x * 64;
    int mi = (tid >> 4) * 4;
    int ni = (tid & 15) * 4;

    float acc[4][4];
#pragma unroll
    for (int a = 0; a < 4; a++)
#pragma unroll
        for (int b = 0; b < 4; b++) acc[a][b] = 0.f;

    for (int ec = 0; ec < 2; ec++) {
        int e0 = ec * 64;
#pragma unroll
        for (int p = 0; p < 16; p++) {
            int q = tid + p * 256;
            int j = q & 63, mm = q >> 6;
            Es[j][mm] = E[(size_t)mm * 128 + e0 + j];
        }
#pragma unroll
        for (int p = 0; p < 16; p++) {
            int q = tid + p * 256;
            int j = q & 63, nn = q >> 6;
            int n = n0 + nn;
            Fs[j][nn] = xg[(size_t)(bt * Nq + n) * Dq + e0 + j] + pos[n * Dq + e0 + j];
        }
        __syncthreads();
#pragma unroll 4
        for (int k = 0; k < 64; k++) {
            float4 e = *reinterpret_cast<const float4*>(&Es[k][mi]);
            float4 f = *reinterpret_cast<const float4*>(&Fs[k][ni]);
            float ea[4] = {e.x, e.y, e.z, e.w};
            float fb[4] = {f.x, f.y, f.z, f.w};
#pragma unroll
            for (int a = 0; a < 4; a++)
#pragma unroll
                for (int b = 0; b < 4; b++) acc[a][b] += ea[a] * fb[b];
        }
        __syncthreads();
    }
#pragma unroll
    for (int a = 0; a < 4; a++) {
        float cm = cvec[mi + a];
#pragma unroll
        for (int b = 0; b < 4; b++)
            logits[(size_t)bt * (Mq * Nq) + (size_t)(mi + a) * Nq + n0 + ni + b] = acc[a][b] + cm;
    }
}

// ---------------- top-16 per row (warp per row, lowest-index tie-break) ----------------
__global__ __launch_bounds__(256) void topk_kernel(const float* __restrict__ logits,
                                                   int* __restrict__ idxout)
{
    int row = blockIdx.x * 8 + (threadIdx.x >> 5);
    int lane = threadIdx.x & 31;
    const float* p = logits + (size_t)row * Nq;
    float v[32];
#pragma unroll
    for (int q = 0; q < 32; q++) v[q] = p[q * 32 + lane];

    for (int t = 0; t < TOPKq; t++) {
        float bvv = v[0]; int bq = 0;
#pragma unroll
        for (int q = 1; q < 32; q++)
            if (v[q] > bvv) { bvv = v[q]; bq = q; }
        int bi = bq * 32 + lane;
#pragma unroll
        for (int o = 16; o > 0; o >>= 1) {
            float ov = __shfl_xor_sync(0xffffffffu, bvv, o);
            int   oi = __shfl_xor_sync(0xffffffffu, bi, o);
            if (ov > bvv || (ov == bvv && oi < bi)) { bvv = ov; bi = oi; }
        }
        if (lane == 0) idxout[row * TOPKq + t] = bi;
#pragma unroll
        for (int q = 0; q < 32; q++)
            if (q * 32 + lane == bi) v[q] = -INFINITY;
    }
}

// ---------------- init dict / counts ----------------
__global__ void init_kernel(float* __restrict__ dict, float* __restrict__ counts)
{
    int i = blockIdx.x * blockDim.x + threadIdx.x;
    if (i < (int)(BTND / 4))
        reinterpret_cast<float4*>(dict)[i] = make_float4(0.f, 0.f, 0.f, 0.f);
    if (i < BTN) counts[i] = 1e-14f;
}

// ---------------- fused gather + 16x16 attention + scatter-add ----------------
__global__ __launch_bounds__(256) void attn_kernel(
    const float* __restrict__ Qg, const float* __restrict__ Kg,
    const float* __restrict__ Vg, const int* __restrict__ idxin,
    float* __restrict__ dict, float* __restrict__ counts)
{
    __shared__ int sidx[16];
    __shared__ float Qs[16][132], Ks[16][132], Vs[16][132];
    __shared__ float Sa[16][16];
    int tid = threadIdx.x;
    int bx = blockIdx.x;            // bt*64 + m
    int bt = bx >> 6;

    if (tid < 16) sidx[tid] = idxin[bx * TOPKq + tid];
    __syncthreads();
#pragma unroll
    for (int p = 0; p < 8; p++) {
        int q = tid + p * 256;
        int k = q >> 7, d = q & 127;
        size_t src = (size_t)(bt * Nq + sidx[k]) * Dq + d;
        Qs[k][d] = Qg[src];
        Ks[k][d] = Kg[src];
        Vs[k][d] = Vg[src];
    }
    __syncthreads();
    {
        int k = tid >> 4, j = tid & 15;
        float s = 0.f;
#pragma unroll 8
        for (int d = 0; d < 128; d++) s += Qs[k][d] * Ks[j][d];
        s *= 0.08838834764831845f;   // 1/sqrt(128)
        float mx = s;
#pragma unroll
        for (int o = 8; o > 0; o >>= 1)
            mx = fmaxf(mx, __shfl_xor_sync(0xffffffffu, mx, o, 16));
        float e = expf(s - mx);
        float sm = e;
#pragma unroll
        for (int o = 8; o > 0; o >>= 1)
            sm += __shfl_xor_sync(0xffffffffu, sm, o, 16);
        Sa[k][j] = e / sm;
    }
    __syncthreads();
#pragma unroll
    for (int p = 0; p < 8; p++) {
        int q = tid + p * 256;
        int k = q >> 7, d = q & 127;
        float v = 0.f;
#pragma unroll
        for (int j = 0; j < 16; j++) v += Sa[k][j] * Vs[j][d];
        atomicAdd(&dict[(size_t)(bt * Nq + sidx[k]) * Dq + d], v);
    }
    if (tid < 16) atomicAdd(&counts[bt * Nq + sidx[tid]], 1.0f);
}

// ---------------- launcher ----------------
extern "C" void kernel_launch(void* const* d_in, const int* in_sizes, int n_in,
                              void* d_out, int out_size)
{
    const float* x       = (const float*)d_in[0];
    const float* eigvec  = (const float*)d_in[1];
    const float* eigval  = (const float*)d_in[2];
    const float* Wq_     = (const float*)d_in[3];
    const float* bq_     = (const float*)d_in[4];
    const float* Wk_     = (const float*)d_in[5];
    const float* bk_     = (const float*)d_in[6];
    const float* Wv_     = (const float*)d_in[7];
    const float* bv_     = (const float*)d_in[8];
    const float* Wo_     = (const float*)d_in[9];
    const float* bo_     = (const float*)d_in[10];
    const float* nodeemb = (const float*)d_in[11];
    const float* ffW1    = (const float*)d_in[12];
    const float* ffb1    = (const float*)d_in[13];
    const float* ffW2    = (const float*)d_in[14];
    const float* ffb2    = (const float*)d_in[15];
    // d_in[16] = adj (unused by the reference computation)
    float* out = (float*)d_out;

    float* S = nullptr;
    cudaGetSymbolAddress((void**)&S, g_scratch);
    float* Qp    = S + OFF_Q;
    float* Kp    = S + OFF_K;
    float* Vp    = S + OFF_V;
    float* dict  = S + OFF_DICT;
    float* val   = S + OFF_VAL;
    float* ff1   = S + OFF_FF1;
    float* logit = S + OFF_LOG;
    float* cnt   = S + OFF_CNT;
    int*   idx   = (int*)(S + OFF_IDX);
    float* posp  = S + OFF_POS;
    float* Ep    = S + OFF_E;
    float* cp    = S + OFF_C;
    __nv_bfloat16* wbf = (__nv_bfloat16*)(S + OFF_WBF);
    // weight slots: 0=Wq, 1=Wk, 2=Wv, 3=Wo, 4=ffW1, 5=ffW2
#define WBH(w) (wbf + (size_t)(w) * 32768)
#define WBL(w) (wbf + (size_t)(w) * 32768 + 16384)

    cudaFuncSetAttribute(gemm_mma<EPI_BIAS, false, true,  false>, cudaFuncAttributeMaxDynamicSharedMemorySize, GM2_SMEM_BYTES);
    cudaFuncSetAttribute(gemm_mma<EPI_LN,   true,  false, true >, cudaFuncAttributeMaxDynamicSharedMemorySize, GM2_SMEM_BYTES);
    cudaFuncSetAttribute(gemm_mma<EPI_RELU, false, false, false>, cudaFuncAttributeMaxDynamicSharedMemorySize, GM2_SMEM_BYTES);
    cudaFuncSetAttribute(gemm_mma<EPI_LN,   false, false, false>, cudaFuncAttributeMaxDynamicSharedMemorySize, GM2_SMEM_BYTES);

    // 0. precompute pos, W bf16 splits, E/c projection (tiny)
    pos_kernel<<<512, 256>>>(eigvec, eigval, posp);
    wsplit_kernel<<<384, 256>>>(Wq_, Wk_, Wv_, Wo_, ffW1, ffW2, wbf);
    eproj_kernel<<<32, 256>>>(Wq_, Wk_, bq_, bk_, nodeemb, Ep, cp);

    // 1. node-selection logits via restructured form (no Q/K dependency)
    logits_kernel<<<dim3(Nq / 64, BT), 256>>>(x, posp, Ep, cp, logit);

    // 2. top-16 per (bt, m)
    topk_kernel<<<NROWS / 8, 256>>>(logit, idx);

    // 3. Q,K,V via pipelined HMMA (smooth paths only now)
    const int GT = BTN / 128;   // 1536
    gemm_mma<EPI_BIAS, false, true, false><<<GT, 256, GM2_SMEM_BYTES>>>(
        x, WBH(0), WBL(0), bq_, nullptr, nullptr, posp, Qp);
    gemm_mma<EPI_BIAS, false, true, false><<<GT, 256, GM2_SMEM_BYTES>>>(
        x, WBH(1), WBL(1), bk_, nullptr, nullptr, posp, Kp);
    gemm_mma<EPI_BIAS, false, true, false><<<GT, 256, GM2_SMEM_BYTES>>>(
        x, WBH(2), WBL(2), bv_, nullptr, nullptr, posp, Vp);

    // 4. init scatter buffers
    init_kernel<<<(int)(BTND / 4 / 256), 256>>>(dict, cnt);

    // 5. gather + local attention + scatter-add
    attn_kernel<<<NROWS, 256>>>(Qp, Kp, Vp, idx, dict, cnt);

    // 6. value = LN((dict/counts) @ Wo + bo + (x + pos))
    gemm_mma<EPI_LN, true, false, true><<<GT, 256, GM2_SMEM_BYTES>>>(
        dict, WBH(3), WBL(3), bo_, x, cnt, posp, val);

    // 7. FFN
    gemm_mma<EPI_RELU, false, false, false><<<GT, 256, GM2_SMEM_BYTES>>>(
        val, WBH(4), WBL(4), ffb1, nullptr, nullptr, posp, ff1);
    gemm_mma<EPI_LN, false, false, false><<<GT, 256, GM2_SMEM_BYTES>>>(
        ff1, WBH(5), WBL(5), ffb2, val, nullptr, posp, out);
}

// round 17
// speedup vs baseline: 1.5914x; 1.0894x over previous
#include <cuda_runtime.h>
#include <cuda_bf16.h>
#include <math.h>
#include <stdint.h>

// ---------------- problem constants ----------------
#define Bq 16
#define Tq 12
#define Nq 1024
#define Dq 128
#define Mq 64
#define TOPKq 16

#define BT (Bq*Tq)                  // 192
#define BTN (BT*Nq)                 // 196608
#define BTND ((size_t)BTN*Dq)       // 25165824
#define NROWS (BT*Mq)               // 12288 topk rows

// ---------------- scratch layout (floats) ----------------
#define OFF_Q    ((size_t)25165824*1)
#define OFF_K    ((size_t)25165824*2)
#define OFF_V    ((size_t)25165824*3)
#define OFF_DICT ((size_t)25165824*4)
#define OFF_VAL  ((size_t)25165824*5)
#define OFF_FF1  ((size_t)25165824*6)
#define OFF_LOG  ((size_t)25165824*7)               // 192*64*1024 = 12582912
#define OFF_CNT  (OFF_LOG + (size_t)12582912)       // 196608
#define OFF_IDX  (OFF_CNT + (size_t)196608)         // 196608 ints
#define OFF_POS  (OFF_IDX + (size_t)196608)         // 131072 floats (pos[n][d])
#define OFF_WBF  (OFF_POS + (size_t)131072)         // 98304 floats = 196608 bf16 (6 weights)
#define OFF_E    (OFF_WBF + (size_t)98304)          // 8192 floats  E[m][k]
#define OFF_C    (OFF_E   + (size_t)8192)           // 64 floats    c[m]
#define TOTAL_SCRATCH (OFF_C + (size_t)64)

__device__ float g_scratch[TOTAL_SCRATCH];

__device__ __forceinline__ uint32_t smem_u32(const void* p) {
    uint32_t a;
    asm("{ .reg .u64 t; cvta.to.shared.u64 t, %1; cvt.u32.u64 %0, t; }" : "=r"(a) : "l"(p));
    return a;
}

enum { EPI_BIAS = 0, EPI_RELU = 1, EPI_LN = 2 };

// ---------------- pos precompute: pos[n][d] = eigvec[d][n] * eigval[d] ----------------
__global__ void pos_kernel(const float* __restrict__ eigvec,
                           const float* __restrict__ eigval,
                           float* __restrict__ posout)
{
    int i = blockIdx.x * 256 + threadIdx.x;   // 0..131071
    int d = i >> 10, n = i & 1023;
    posout[n * Dq + d] = eigvec[(size_t)d * Nq + n] * eigval[d];
}

// ---------------- W bf16 hi/lo split precompute (B = W^T layout [n][k]) ----------------
__global__ void wsplit_kernel(const float* __restrict__ W0, const float* __restrict__ W1,
                              const float* __restrict__ W2, const float* __restrict__ W3,
                              const float* __restrict__ W4, const float* __restrict__ W5,
                              __nv_bfloat16* __restrict__ outb)
{
    int g = blockIdx.x * 256 + threadIdx.x;   // 0..98303
    int w = g >> 14;
    int i = g & 16383;
    int n = i & 127, k = i >> 7;
    const float* W = (w == 0) ? W0 : (w == 1) ? W1 : (w == 2) ? W2
                   : (w == 3) ? W3 : (w == 4) ? W4 : W5;
    float v = W[(size_t)k * Dq + n];
    __nv_bfloat16 h = __float2bfloat16_rn(v);
    __nv_bfloat16 l = __float2bfloat16_rn(v - __bfloat162float(h));
    __nv_bfloat16* basep = outb + (size_t)w * 32768;
    basep[n * 128 + k] = h;
    basep[16384 + n * 128 + k] = l;
}

// ---------------- E projection: E[m][k] = sum_d Wq[k][d]emb[m][d] + Wk[k][d]emb[m][128+d] ----
__global__ void eproj_kernel(const float* __restrict__ Wq, const float* __restrict__ Wk,
                             const float* __restrict__ bq, const float* __restrict__ bk,
                             const float* __restrict__ emb,
                             float* __restrict__ E, float* __restrict__ cvec)
{
    int i = blockIdx.x * 256 + threadIdx.x;   // 0..8191
    int m = i >> 7, k = i & 127;
    const float* em = emb + (size_t)m * 256;
    const float* wq = Wq + (size_t)k * Dq;
    const float* wk = Wk + (size_t)k * Dq;
    float s = 0.f;
#pragma unroll 8
    for (int d = 0; d < 128; d++)
        s += wq[d] * em[d] + wk[d] * em[128 + d];
    E[m * 128 + k] = s;
    if (k == 0) {
        float cc = 0.f;
#pragma unroll 8
        for (int d = 0; d < 128; d++)
            cc += em[d] * bq[d] + em[128 + d] * bk[d];
        cvec[m] = cc;
    }
}

// ================= shared HMMA helpers =========
#define ROW2     144         // bf16 row stride bytes (64 bf16 + pad)
#define TILE_B   18432       // 128 * 144

__device__ __forceinline__ void ldsm_x4(uint32_t* r, uint32_t addr) {
    asm volatile("ldmatrix.sync.aligned.m8n8.x4.shared.b16 {%0,%1,%2,%3}, [%4];"
        : "=r"(r[0]), "=r"(r[1]), "=r"(r[2]), "=r"(r[3]) : "r"(addr));
}
__device__ __forceinline__ void mma_bf16(float* d, const uint32_t* a, const uint32_t* b) {
    asm volatile("mma.sync.aligned.m16n8k16.row.col.f32.bf16.bf16.f32 "
        "{%0,%1,%2,%3}, {%4,%5,%6,%7}, {%8,%9}, {%0,%1,%2,%3};"
        : "+f"(d[0]), "+f"(d[1]), "+f"(d[2]), "+f"(d[3])
        : "r"(a[0]), "r"(a[1]), "r"(a[2]), "r"(a[3]), "r"(b[0]), "r"(b[1]));
}

__device__ __forceinline__ void split4_bf16(const float* f, uint2& hi, uint2& lo) {
    unsigned short h[4], l[4];
#pragma unroll
    for (int i = 0; i < 4; i++) {
        __nv_bfloat16 bh = __float2bfloat16_rn(f[i]);
        float fh = __bfloat162float(bh);
        __nv_bfloat16 bl = __float2bfloat16_rn(f[i] - fh);
        h[i] = __bfloat16_as_ushort(bh);
        l[i] = __bfloat16_as_ushort(bl);
    }
    hi = make_uint2((uint32_t)h[0] | ((uint32_t)h[1] << 16), (uint32_t)h[2] | ((uint32_t)h[3] << 16));
    lo = make_uint2((uint32_t)l[0] | ((uint32_t)l[1] << 16), (uint32_t)l[2] | ((uint32_t)l[3] << 16));
}

// A hi at Ab, lo at Ab+TILE_B; B hi at Bb, lo at Bb+TILE_B (one 64-wide K stage)
__device__ __forceinline__ void mma_stage2(uint32_t Ab, uint32_t Bb,
                                           uint32_t a_row, uint32_t a_csel,
                                           uint32_t b_rowb, uint32_t b_csel,
                                           float (*acc)[8][4])
{
#pragma unroll
    for (int ks = 0; ks < 4; ks++) {
        uint32_t kb = (uint32_t)(ks * 32);
        uint32_t Ahf[2][4], Alf[2][4];
#pragma unroll
        for (int mi = 0; mi < 2; mi++) {
            uint32_t ad = Ab + (a_row + mi * 16) * ROW2 + kb + a_csel;
            ldsm_x4(Ahf[mi], ad);
            ldsm_x4(Alf[mi], ad + TILE_B);
        }
        uint32_t Bhf[8][2], Blf[8][2];
#pragma unroll
        for (int np = 0; np < 4; np++) {
            uint32_t bd = Bb + (b_rowb + np * 16) * ROW2 + kb + b_csel;
            uint32_t r[4];
            ldsm_x4(r, bd);
            Bhf[np*2][0] = r[0]; Bhf[np*2][1] = r[1];
            Bhf[np*2+1][0] = r[2]; Bhf[np*2+1][1] = r[3];
            ldsm_x4(r, bd + TILE_B);
            Blf[np*2][0] = r[0]; Blf[np*2][1] = r[1];
            Blf[np*2+1][0] = r[2]; Blf[np*2+1][1] = r[3];
        }
#pragma unroll
        for (int mi = 0; mi < 2; mi++)
#pragma unroll
            for (int ni = 0; ni < 8; ni++) {
                mma_bf16(acc[mi][ni], Ahf[mi], Bhf[ni]);
                mma_bf16(acc[mi][ni], Ahf[mi], Blf[ni]);
                mma_bf16(acc[mi][ni], Alf[mi], Bhf[ni]);
            }
    }
}

// ================= fused QKV GEMM: A (x+pos) converted once, 3 weights streamed =========
#define SM3_BIAS 0                    // 3 * 512
#define SM3_A    2048                 // 4*TILE_B (stage0 hi/lo, stage1 hi/lo)
#define SM3_B0   (2048 + 4*TILE_B)    // 75776
#define SM3_B1   (SM3_B0 + 4*TILE_B)  // 149504
#define QKV_SMEM_BYTES (SM3_B1 + 4*TILE_B)  // 223232

__device__ __forceinline__ void issue_B(uint32_t bufbase, const __nv_bfloat16* Bh,
                                        const __nv_bfloat16* Bl, int tid)
{
#pragma unroll
    for (int s = 0; s < 2; s++) {
        uint32_t base = bufbase + s * 2 * TILE_B;
#pragma unroll
        for (int t = 0; t < 2; t++) {
            const __nv_bfloat16* src = t ? Bl : Bh;
#pragma unroll
            for (int p = 0; p < 4; p++) {
                int q = tid + p * 256;
                int row = q >> 3, c = q & 7;
                uint32_t sa = base + (uint32_t)(t * TILE_B + row * ROW2 + c * 16);
                const void* ga = src + row * 128 + s * 64 + c * 8;
                asm volatile("cp.async.cg.shared.global [%0], [%1], 16;" :: "r"(sa), "l"(ga));
            }
        }
    }
    asm volatile("cp.async.commit_group;");
}

__global__ __launch_bounds__(256) void gemm_qkv(
    const float* __restrict__ A, const float* __restrict__ pos,
    const __nv_bfloat16* __restrict__ wbf,   // slots 0,1,2 = Wq,Wk,Wv
    const float* __restrict__ bq, const float* __restrict__ bk, const float* __restrict__ bv,
    float* __restrict__ outQ, float* __restrict__ outK, float* __restrict__ outV)
{
    extern __shared__ char smem[];
    uint32_t sb = smem_u32(smem);
    int tid = threadIdx.x;
    int lane = tid & 31, wid = tid >> 5;
    int base = blockIdx.x * 128;

    if (tid < 128) {
        ((float*)(smem + SM3_BIAS))[tid]       = bq[tid];
        ((float*)(smem + SM3_BIAS + 512))[tid] = bk[tid];
        ((float*)(smem + SM3_BIAS + 1024))[tid] = bv[tid];
    }

    // B prefetch: w0 -> buf0, w1 -> buf1
    issue_B(sb + SM3_B0, wbf,                 wbf + 16384, tid);
    issue_B(sb + SM3_B1, wbf + 32768,         wbf + 32768 + 16384, tid);

    // ---- A: (x+pos) -> bf16 hi/lo, both K stages, once ----
    const float4* A4 = reinterpret_cast<const float4*>(A);
    const float4* pos4 = reinterpret_cast<const float4*>(pos);
#pragma unroll
    for (int i = 0; i < 16; i++) {
        int f = tid + 256 * i;
        int row = f >> 5, c4 = f & 31;
        int grow = base + row;
        float4 v = A4[(size_t)grow * 32 + c4];
        float4 pv = pos4[(grow & (Nq - 1)) * 32 + c4];
        v.x += pv.x; v.y += pv.y; v.z += pv.z; v.w += pv.w;
        float ff[4] = {v.x, v.y, v.z, v.w};
        uint2 hi, lo; split4_bf16(ff, hi, lo);
        int st = c4 >> 4, c4s = c4 & 15;
        uint32_t off = (uint32_t)(SM3_A + st * 2 * TILE_B + row * ROW2 + c4s * 8);
        *reinterpret_cast<uint2*>(smem + off) = hi;
        *reinterpret_cast<uint2*>(smem + off + TILE_B) = lo;
    }

    int m0 = (wid & 3) * 32, n0 = (wid >> 2) * 64;
    uint32_t a_row  = (uint32_t)(m0 + (lane & 7) + ((lane >> 3) & 1) * 8);
    uint32_t a_csel = (uint32_t)((lane >> 4) * 16);
    uint32_t b_rowb = (uint32_t)(n0 + (lane & 7) + (lane >> 4) * 8);
    uint32_t b_csel = (uint32_t)(((lane >> 3) & 1) * 16);
    int dr = lane >> 2, dc = (lane & 3) * 2;

    float acc[2][8][4];
    float* outs[3] = {outQ, outK, outV};

    asm volatile("cp.async.wait_group 1;");   // buf0 (w0) ready
    __syncthreads();                           // A + buf0 visible to all

#pragma unroll
    for (int w = 0; w < 3; w++) {
        uint32_t Bbuf = sb + ((w & 1) ? SM3_B1 : SM3_B0);
#pragma unroll
        for (int mi = 0; mi < 2; mi++)
#pragma unroll
            for (int ni = 0; ni < 8; ni++)
#pragma unroll
                for (int c = 0; c < 4; c++) acc[mi][ni][c] = 0.f;

        mma_stage2(sb + SM3_A,              Bbuf,              a_row, a_csel, b_rowb, b_csel, acc);
        mma_stage2(sb + SM3_A + 2 * TILE_B, Bbuf + 2 * TILE_B, a_row, a_csel, b_rowb, b_csel, acc);

        if (w == 0) {
            __syncthreads();   // all warps done reading buf0
            issue_B(sb + SM3_B0, wbf + 65536, wbf + 65536 + 16384, tid);  // w2 -> buf0
        }

        // ---- epilogue: direct fragment store + bias ----
        const float* bias_s = (const float*)(smem + SM3_BIAS + w * 512);
        float* outw = outs[w];
#pragma unroll
        for (int mi = 0; mi < 2; mi++)
#pragma unroll
            for (int ni = 0; ni < 8; ni++) {
                int m = m0 + mi * 16 + dr, n = n0 + ni * 8 + dc;
                float b0 = bias_s[n], b1 = bias_s[n + 1];
                *reinterpret_cast<float2*>(&outw[(size_t)(base + m) * Dq + n]) =
                    make_float2(acc[mi][ni][0] + b0, acc[mi][ni][1] + b1);
                *reinterpret_cast<float2*>(&outw[(size_t)(base + m + 8) * Dq + n]) =
                    make_float2(acc[mi][ni][2] + b0, acc[mi][ni][3] + b1);
            }

        if (w == 0) {
            asm volatile("cp.async.wait_group 1;");   // buf1 (w1) ready
            __syncthreads();
        } else if (w == 1) {
            asm volatile("cp.async.wait_group 0;");   // buf0 (w2) ready
            __syncthreads();
        }
    }
}

// ================= mma.sync bf16 3-pass GEMM, K-split pipelined (Wo/FF1/FF2) =========
#define SM2_BIAS 0           // 512B
#define SM2_MEAN 512         // 512B
#define SM2_RSTD 1024        // 512B
#define SM2_T    2048        // stage0 base; stage1 at +STAGE_BYTES
#define STAGE_BYTES (4*TILE_B)   // AH, AL, BH, BL
#define GM2_SMEM_BYTES (2048 + 2*STAGE_BYTES)   // 149504

__device__ __forceinline__ void mma_stage(uint32_t SB, uint32_t a_row, uint32_t a_csel,
                                          uint32_t b_rowb, uint32_t b_csel,
                                          float (*acc)[8][4])
{
    mma_stage2(SB, SB + 2 * TILE_B, a_row, a_csel, b_rowb, b_csel, acc);
}

template<int EPI, bool ROWSCALE, bool POSADD, bool RESPOS>
__global__ __launch_bounds__(256) void gemm_mma(
    const float* __restrict__ A,
    const __nv_bfloat16* __restrict__ Bh_pre,
    const __nv_bfloat16* __restrict__ Bl_pre,
    const float* __restrict__ bias, const float* __restrict__ resid,
    const float* __restrict__ rowdiv, const float* __restrict__ pos,
    float* __restrict__ out)
{
    extern __shared__ char smem[];
    uint32_t sb = smem_u32(smem);
    int tid = threadIdx.x;
    int lane = tid & 31, wid = tid >> 5;
    int base = blockIdx.x * 128;

    if (tid < 128) ((float*)(smem + SM2_BIAS))[tid] = bias[tid];

    // ---- B tiles (both K-stages) via cp.async from precomputed bf16 split ----
#pragma unroll
    for (int s = 0; s < 2; s++) {
        uint32_t bbase = sb + SM2_T + s * STAGE_BYTES + 2 * TILE_B;
#pragma unroll
        for (int t = 0; t < 2; t++) {
            const __nv_bfloat16* src = t ? Bl_pre : Bh_pre;
#pragma unroll
            for (int p = 0; p < 4; p++) {
                int q = tid + p * 256;
                int row = q >> 3, c = q & 7;
                uint32_t sa = bbase + (uint32_t)(t * TILE_B + row * ROW2 + c * 16);
                const void* ga = src + row * 128 + s * 64 + c * 8;
                asm volatile("cp.async.cg.shared.global [%0], [%1], 16;" :: "r"(sa), "l"(ga));
            }
        }
        asm volatile("cp.async.commit_group;");
    }

    const float4* A4 = reinterpret_cast<const float4*>(A);
    const float4* pos4 = reinterpret_cast<const float4*>(pos);

    // ---- stage0 A: load + bf16 hi/lo convert + store ----
#pragma unroll
    for (int i = 0; i < 8; i++) {
        int f = tid + 256 * i;
        int row = f >> 4, c4 = f & 15;
        int grow = base + row;
        float4 v = A4[(size_t)grow * 32 + c4];
        if (POSADD) {
            float4 pv = pos4[(grow & (Nq - 1)) * 32 + c4];
            v.x += pv.x; v.y += pv.y; v.z += pv.z; v.w += pv.w;
        }
        if (ROWSCALE) {
            float rs = 1.0f / rowdiv[grow];
            v.x *= rs; v.y *= rs; v.z *= rs; v.w *= rs;
        }
        float ff[4] = {v.x, v.y, v.z, v.w};
        uint2 hi, lo; split4_bf16(ff, hi, lo);
        uint32_t off = (uint32_t)(SM2_T + row * ROW2 + c4 * 8);
        *reinterpret_cast<uint2*>(smem + off) = hi;
        *reinterpret_cast<uint2*>(smem + off + TILE_B) = lo;
    }
    asm volatile("cp.async.wait_group 1;");
    __syncthreads();

    // ---- prefetch stage1 A into registers (LDGs fly during stage0 MMA) ----
    float4 a1[8];
#pragma unroll
    for (int i = 0; i < 8; i++) {
        int f = tid + 256 * i;
        int row = f >> 4, c4 = f & 15;
        int grow = base + row;
        float4 v = A4[(size_t)grow * 32 + 16 + c4];
        if (POSADD) {
            float4 pv = pos4[(grow & (Nq - 1)) * 32 + 16 + c4];
            v.x += pv.x; v.y += pv.y; v.z += pv.z; v.w += pv.w;
        }
        if (ROWSCALE) {
            float rs = 1.0f / rowdiv[grow];
            v.x *= rs; v.y *= rs; v.z *= rs; v.w *= rs;
        }
        a1[i] = v;
    }

    int m0 = (wid & 3) * 32, n0 = (wid >> 2) * 64;
    uint32_t a_row  = (uint32_t)(m0 + (lane & 7) + ((lane >> 3) & 1) * 8);
    uint32_t a_csel = (uint32_t)((lane >> 4) * 16);
    uint32_t b_rowb = (uint32_t)(n0 + (lane & 7) + (lane >> 4) * 8);
    uint32_t b_csel = (uint32_t)(((lane >> 3) & 1) * 16);

    float acc[2][8][4];
#pragma unroll
    for (int mi = 0; mi < 2; mi++)
#pragma unroll
        for (int ni = 0; ni < 8; ni++)
#pragma unroll
            for (int c = 0; c < 4; c++) acc[mi][ni][c] = 0.f;

    mma_stage(sb + SM2_T, a_row, a_csel, b_rowb, b_csel, acc);

    // ---- convert + store stage1 A ----
#pragma unroll
    for (int i = 0; i < 8; i++) {
        int f = tid + 256 * i;
        int row = f >> 4, c4 = f & 15;
        float ff[4] = {a1[i].x, a1[i].y, a1[i].z, a1[i].w};
        uint2 hi, lo; split4_bf16(ff, hi, lo);
        uint32_t off = (uint32_t)(SM2_T + STAGE_BYTES + row * ROW2 + c4 * 8);
        *reinterpret_cast<uint2*>(smem + off) = hi;
        *reinterpret_cast<uint2*>(smem + off + TILE_B) = lo;
    }
    asm volatile("cp.async.wait_group 0;");
    __syncthreads();

    mma_stage(sb + SM2_T + STAGE_BYTES, a_row, a_csel, b_rowb, b_csel, acc);

    __syncthreads();

    // ---- stage D in SMEM (f32, stride 132 floats, overlays stage0) ----
    {
        float* Ds = (float*)(smem + SM2_T);
        int dr = lane >> 2, dc = (lane & 3) * 2;
#pragma unroll
        for (int mi = 0; mi < 2; mi++)
#pragma unroll
            for (int ni = 0; ni < 8; ni++) {
                int m = m0 + mi * 16 + dr, n = n0 + ni * 8 + dc;
                *reinterpret_cast<float2*>(&Ds[m * 132 + n]) =
                    make_float2(acc[mi][ni][0], acc[mi][ni][1]);
                *reinterpret_cast<float2*>(&Ds[(m + 8) * 132 + n]) =
                    make_float2(acc[mi][ni][2], acc[mi][ni][3]);
            }
    }
    __syncthreads();

    float4* ds4 = (float4*)(smem + SM2_T);
    const float4* bias4 = (const float4*)(smem + SM2_BIAS);
    float4* out4 = (float4*)out;

    if (EPI == EPI_LN) {
        const float4* resid4 = (const float4*)resid;
#pragma unroll
        for (int i = 0; i < 16; i++) {
            int f = tid + 256 * i;
            int row = f >> 5, c4 = f & 31;
            float4 d = ds4[row * 33 + c4];
            float4 b = bias4[c4];
            float4 rr = resid4[(size_t)(base + row) * 32 + c4];
            if (RESPOS) {
                float4 pv = pos4[((base + row) & (Nq - 1)) * 32 + c4];
                rr.x += pv.x; rr.y += pv.y; rr.z += pv.z; rr.w += pv.w;
            }
            d.x += b.x + rr.x; d.y += b.y + rr.y;
            d.z += b.z + rr.z; d.w += b.w + rr.w;
            ds4[row * 33 + c4] = d;
        }
        __syncthreads();
        if (tid < 128) {
            const float* Ds = (const float*)(smem + SM2_T);
            float s = 0.f;
#pragma unroll 8
            for (int c = 0; c < 128; c++) s += Ds[tid * 132 + c];
            float mean = s * (1.0f / 128.0f);
            float sq = 0.f;
#pragma unroll 8
            for (int c = 0; c < 128; c++) {
                float dv = Ds[tid * 132 + c] - mean;
                sq += dv * dv;
            }
            ((float*)(smem + SM2_MEAN))[tid] = mean;
            ((float*)(smem + SM2_RSTD))[tid] = rsqrtf(sq * (1.0f / 128.0f) + 1e-5f);
        }
        __syncthreads();
        const float* meanS = (const float*)(smem + SM2_MEAN);
        const float* rstdS = (const float*)(smem + SM2_RSTD);
#pragma unroll
        for (int i = 0; i < 16; i++) {
            int f = tid + 256 * i;
            int row = f >> 5, c4 = f & 31;
            float4 d = ds4[row * 33 + c4];
            float mn = meanS[row], rs = rstdS[row];
            d.x = (d.x - mn) * rs; d.y = (d.y - mn) * rs;
            d.z = (d.z - mn) * rs; d.w = (d.w - mn) * rs;
            out4[(size_t)(base + row) * 32 + c4] = d;
        }
    } else {
#pragma unroll
        for (int i = 0; i < 16; i++) {
            int f = tid + 256 * i;
            int row = f >> 5, c4 = f & 31;
            float4 d = ds4[row * 33 + c4];
            float4 b = bias4[c4];
            d.x += b.x; d.y += b.y; d.z += b.z; d.w += b.w;
            if (EPI == EPI_RELU) {
                d.x = fmaxf(d.x, 0.f); d.y = fmaxf(d.y, 0.f);
                d.z = fmaxf(d.z, 0.f); d.w = fmaxf(d.w, 0.f);
            }
            out4[(size_t)(base + row) * 32 + c4] = d;
        }
    }
}

// ---------------- logits: L[bt][m][n] = (x+pos)[bt,n,:]·E[m,:] + c[m] ----------------
__global__ __launch_bounds__(256) void logits_kernel(
    const float* __restrict__ xg, const float* __restrict__ pos,
    const float* __restrict__ E, const float* __restrict__ cvec,
    float* __restrict__ logits)
{
    __shared__ float Es[64][68];   // k-chunk x m (16B-aligned rows)
    __shared__ float Fs[64][68];   // k-chunk x n
    int tid = threadIdx.x;
    int bt = blockIdx.y;
    int n0 = blockIdx.x * 64;
    int mi = (tid >> 4) * 4;
    int ni = (tid & 15) * 4;

    float acc[4][4];
#pragma unroll
    for (int a = 0; a < 4; a++)
#pragma unroll
        for (int b = 0; b < 4; b++) acc[a][b] = 0.f;

    for (int ec = 0; ec < 2; ec++) {
        int e0 = ec * 64;
#pragma unroll
        for (int p = 0; p < 16; p++) {
            int q = tid + p * 256;
            int j = q & 63, mm = q >> 6;
            Es[j][mm] = E[(size_t)mm * 128 + e0 + j];
        }
#pragma unroll
        for (int p = 0; p < 16; p++) {
            int q = tid + p * 256;
            int j = q & 63, nn = q >> 6;
            int n = n0 + nn;
            Fs[j][nn] = xg[(size_t)(bt * Nq + n) * Dq + e0 + j] + pos[n * Dq + e0 + j];
        }
        __syncthreads();
#pragma unroll 4
        for (int k = 0; k < 64; k++) {
            float4 e = *reinterpret_cast<const float4*>(&Es[k][mi]);
            float4 f = *reinterpret_cast<const float4*>(&Fs[k][ni]);
            float ea[4] = {e.x, e.y, e.z, e.w};
            float fb[4] = {f.x, f.y, f.z, f.w};
#pragma unroll
            for (int a = 0; a < 4; a++)
#pragma unroll
                for (int b = 0; b < 4; b++) acc[a][b] += ea[a] * fb[b];
        }
        __syncthreads();
    }
#pragma unroll
    for (int a = 0; a < 4; a++) {
        float cm = cvec[mi + a];
#pragma unroll
        for (int b = 0; b < 4; b++)
            logits[(size_t)bt * (Mq * Nq) + (size_t)(mi + a) * Nq + n0 + ni + b] = acc[a][b] + cm;
    }
}

// ---------------- top-16 per row (warp per row, lowest-index tie-break) ----------------
__global__ __launch_bounds__(256) void topk_kernel(const float* __restrict__ logits,
                                                   int* __restrict__ idxout)
{
    int row = blockIdx.x * 8 + (threadIdx.x >> 5);
    int lane = threadIdx.x & 31;
    const float* p = logits + (size_t)row * Nq;
    float v[32];
#pragma unroll
    for (int q = 0; q < 32; q++) v[q] = p[q * 32 + lane];

    for (int t = 0; t < TOPKq; t++) {
        float bvv = v[0]; int bq = 0;
#pragma unroll
        for (int q = 1; q < 32; q++)
            if (v[q] > bvv) { bvv = v[q]; bq = q; }
        int bi = bq * 32 + lane;
#pragma unroll
        for (int o = 16; o > 0; o >>= 1) {
            float ov = __shfl_xor_sync(0xffffffffu, bvv, o);
            int   oi = __shfl_xor_sync(0xffffffffu, bi, o);
            if (ov > bvv || (ov == bvv && oi < bi)) { bvv = ov; bi = oi; }
        }
        if (lane == 0) idxout[row * TOPKq + t] = bi;
#pragma unroll
        for (int q = 0; q < 32; q++)
            if (q * 32 + lane == bi) v[q] = -INFINITY;
    }
}

// ---------------- init dict / counts ----------------
__global__ void init_kernel(float* __restrict__ dict, float* __restrict__ counts)
{
    int i = blockIdx.x * blockDim.x + threadIdx.x;
    if (i < (int)(BTND / 4))
        reinterpret_cast<float4*>(dict)[i] = make_float4(0.f, 0.f, 0.f, 0.f);
    if (i < BTN) counts[i] = 1e-14f;
}

// ---------------- fused gather + 16x16 attention + scatter-add ----------------
__global__ __launch_bounds__(256) void attn_kernel(
    const float* __restrict__ Qg, const float* __restrict__ Kg,
    const float* __restrict__ Vg, const int* __restrict__ idxin,
    float* __restrict__ dict, float* __restrict__ counts)
{
    __shared__ int sidx[16];
    __shared__ float Qs[16][132], Ks[16][132], Vs[16][132];
    __shared__ float Sa[16][16];
    int tid = threadIdx.x;
    int bx = blockIdx.x;            // bt*64 + m
    int bt = bx >> 6;

    if (tid < 16) sidx[tid] = idxin[bx * TOPKq + tid];
    __syncthreads();
#pragma unroll
    for (int p = 0; p < 8; p++) {
        int q = tid + p * 256;
        int k = q >> 7, d = q & 127;
        size_t src = (size_t)(bt * Nq + sidx[k]) * Dq + d;
        Qs[k][d] = Qg[src];
        Ks[k][d] = Kg[src];
        Vs[k][d] = Vg[src];
    }
    __syncthreads();
    {
        int k = tid >> 4, j = tid & 15;
        float s = 0.f;
#pragma unroll 8
        for (int d = 0; d < 128; d++) s += Qs[k][d] * Ks[j][d];
        s *= 0.08838834764831845f;   // 1/sqrt(128)
        float mx = s;
#pragma unroll
        for (int o = 8; o > 0; o >>= 1)
            mx = fmaxf(mx, __shfl_xor_sync(0xffffffffu, mx, o, 16));
        float e = expf(s - mx);
        float sm = e;
#pragma unroll
        for (int o = 8; o > 0; o >>= 1)
            sm += __shfl_xor_sync(0xffffffffu, sm, o, 16);
        Sa[k][j] = e / sm;
    }
    __syncthreads();
#pragma unroll
    for (int p = 0; p < 8; p++) {
        int q = tid + p * 256;
        int k = q >> 7, d = q & 127;
        float v = 0.f;
#pragma unroll
        for (int j = 0; j < 16; j++) v += Sa[k][j] * Vs[j][d];
        atomicAdd(&dict[(size_t)(bt * Nq + sidx[k]) * Dq + d], v);
    }
    if (tid < 16) atomicAdd(&counts[bt * Nq + sidx[tid]], 1.0f);
}

// ---------------- launcher ----------------
extern "C" void kernel_launch(void* const* d_in, const int* in_sizes, int n_in,
                              void* d_out, int out_size)
{
    const float* x       = (const float*)d_in[0];
    const float* eigvec  = (const float*)d_in[1];
    const float* eigval  = (const float*)d_in[2];
    const float* Wq_     = (const float*)d_in[3];
    const float* bq_     = (const float*)d_in[4];
    const float* Wk_     = (const float*)d_in[5];
    const float* bk_     = (const float*)d_in[6];
    const float* Wv_     = (const float*)d_in[7];
    const float* bv_     = (const float*)d_in[8];
    const float* Wo_     = (const float*)d_in[9];
    const float* bo_     = (const float*)d_in[10];
    const float* nodeemb = (const float*)d_in[11];
    const float* ffW1    = (const float*)d_in[12];
    const float* ffb1    = (const float*)d_in[13];
    const float* ffW2    = (const float*)d_in[14];
    const float* ffb2    = (const float*)d_in[15];
    // d_in[16] = adj (unused by the reference computation)
    float* out = (float*)d_out;

    float* S = nullptr;
    cudaGetSymbolAddress((void**)&S, g_scratch);
    float* Qp    = S + OFF_Q;
    float* Kp    = S + OFF_K;
    float* Vp    = S + OFF_V;
    float* dict  = S + OFF_DICT;
    float* val   = S + OFF_VAL;
    float* ff1   = S + OFF_FF1;
    float* logit = S + OFF_LOG;
    float* cnt   = S + OFF_CNT;
    int*   idx   = (int*)(S + OFF_IDX);
    float* posp  = S + OFF_POS;
    float* Ep    = S + OFF_E;
    float* cp    = S + OFF_C;
    __nv_bfloat16* wbf = (__nv_bfloat16*)(S + OFF_WBF);
    // weight slots: 0=Wq, 1=Wk, 2=Wv, 3=Wo, 4=ffW1, 5=ffW2
#define WBH(w) (wbf + (size_t)(w) * 32768)
#define WBL(w) (wbf + (size_t)(w) * 32768 + 16384)

    cudaFuncSetAttribute(gemm_qkv, cudaFuncAttributeMaxDynamicSharedMemorySize, QKV_SMEM_BYTES);
    cudaFuncSetAttribute(gemm_mma<EPI_LN,   true,  false, true >, cudaFuncAttributeMaxDynamicSharedMemorySize, GM2_SMEM_BYTES);
    cudaFuncSetAttribute(gemm_mma<EPI_RELU, false, false, false>, cudaFuncAttributeMaxDynamicSharedMemorySize, GM2_SMEM_BYTES);
    cudaFuncSetAttribute(gemm_mma<EPI_LN,   false, false, false>, cudaFuncAttributeMaxDynamicSharedMemorySize, GM2_SMEM_BYTES);

    // 0. precompute pos, W bf16 splits, E/c projection (tiny)
    pos_kernel<<<512, 256>>>(eigvec, eigval, posp);
    wsplit_kernel<<<384, 256>>>(Wq_, Wk_, Wv_, Wo_, ffW1, ffW2, wbf);
    eproj_kernel<<<32, 256>>>(Wq_, Wk_, bq_, bk_, nodeemb, Ep, cp);

    // 1. node-selection logits via restructured form (no Q/K dependency)
    logits_kernel<<<dim3(Nq / 64, BT), 256>>>(x, posp, Ep, cp, logit);

    // 2. top-16 per (bt, m)
    topk_kernel<<<NROWS / 8, 256>>>(logit, idx);

    // 3. Q,K,V fused: A converted once, 3 weights streamed
    const int GT = BTN / 128;   // 1536
    gemm_qkv<<<GT, 256, QKV_SMEM_BYTES>>>(x, posp, wbf, bq_, bk_, bv_, Qp, Kp, Vp);

    // 4. init scatter buffers
    init_kernel<<<(int)(BTND / 4 / 256), 256>>>(dict, cnt);

    // 5. gather + local attention + scatter-add
    attn_kernel<<<NROWS, 256>>>(Qp, Kp, Vp, idx, dict, cnt);

    // 6. value = LN((dict/counts) @ Wo + bo + (x + pos))
    gemm_mma<EPI_LN, true, false, true><<<GT, 256, GM2_SMEM_BYTES>>>(
        dict, WBH(3), WBL(3), bo_, x, cnt, posp, val);

    // 7. FFN
    gemm_mma<EPI_RELU, false, false, false><<<GT, 256, GM2_SMEM_BYTES>>>(
        val, WBH(4), WBL(4), ffb1, nullptr, nullptr, posp, ff1);
    gemm_mma<EPI_LN, false, false, false><<<GT, 256, GM2_SMEM_BYTES>>>(
        ff1, WBH(5), WBL(5), ffb2, val, nullptr, posp, out);
}